// round 1
// baseline (speedup 1.0000x reference)
#include <cuda_runtime.h>
#include <math.h>
#include <stdint.h>

// Problem constants
#define BB 4
#define SS 2048
#define DD 1024
#define HH 256
#define EE 4
#define FF 4096
#define MMEM 64
#define BS (BB*SS)          // 8192
#define KSP 204             // max(1, int(S*0.1))

// ---------------- scratch (static device globals; no allocation allowed) ----
__device__ float g_qkv_loc[(size_t)BS*3*HH];   // 25MB
__device__ float g_qkv_sp [(size_t)BS*3*HH];   // 25MB
__device__ float g_scores [(size_t)BB*SS*SS];  // 67MB (reused local->sparse)
__device__ float g_cat    [(size_t)BS*4*HH];   // 33MB
__device__ float g_xp     [(size_t)BS*HH];
__device__ float g_ret    [(size_t)BS*HH];
__device__ float g_mlog   [(size_t)BS*MMEM];
__device__ float g_pp     [(size_t)BS*HH];
__device__ float g_mid    [(size_t)BS*2*HH];
__device__ float g_x2     [(size_t)BS*DD];
__device__ float g_rw     [(size_t)BS*EE];
__device__ float g_h      [(size_t)BS*FF];     // 134MB

// ---------------- generic tiled SGEMM ---------------------------------------
// C[M,N] = alpha * A[M,K] @ op(B) (+bias) (gelu) (+addend) ; op(B)=B or B^T
// ROWSCALE: C[m,n] += rowscale[m*rss] * v ; ACCUM: C += v ; else C = v
// C2 (optional): C2[m*ldc+n] = v (second copy of the epilogue value)
template<bool TRANSB, bool DOGELU, bool ACCUM, bool ROWSCALE>
__global__ void __launch_bounds__(256, 2) gemm_k(
    const float* __restrict__ A, int lda,
    const float* __restrict__ Bp, int ldb,
    float* __restrict__ C, int ldc,
    float* __restrict__ C2,
    int M, int N, int K, float alpha,
    const float* __restrict__ bias,
    const float* __restrict__ rowscale, int rss,
    const float* __restrict__ addend, int ldadd)
{
    __shared__ float As[8][128];
    __shared__ float Bs[8][128];
    const int tid = threadIdx.x;
    const int m0 = blockIdx.y * 128, n0 = blockIdx.x * 128;
    const int tx = tid & 15, ty = tid >> 4;

    float acc[8][8];
#pragma unroll
    for (int i = 0; i < 8; i++)
#pragma unroll
        for (int j = 0; j < 8; j++) acc[i][j] = 0.f;

    const int arow = tid >> 1, acol = (tid & 1) * 4;
    const int brow_t = tid >> 1, bcol_t = (tid & 1) * 4;   // TRANSB mapping (n,k)
    const int brow_n = tid >> 5, bcol_n = (tid & 31) * 4;  // NN mapping (k,n)

    for (int k0 = 0; k0 < K; k0 += 8) {
        float4 av = make_float4(0.f, 0.f, 0.f, 0.f);
        if (m0 + arow < M)
            av = *(const float4*)(A + (size_t)(m0 + arow) * lda + (k0 + acol));
        float4 bv = make_float4(0.f, 0.f, 0.f, 0.f);
        if (TRANSB) {
            if (n0 + brow_t < N)
                bv = *(const float4*)(Bp + (size_t)(n0 + brow_t) * ldb + (k0 + bcol_t));
        } else {
            if (n0 + bcol_n < N)
                bv = *(const float4*)(Bp + (size_t)(k0 + brow_n) * ldb + (n0 + bcol_n));
        }
        __syncthreads();
        As[acol + 0][arow] = av.x; As[acol + 1][arow] = av.y;
        As[acol + 2][arow] = av.z; As[acol + 3][arow] = av.w;
        if (TRANSB) {
            Bs[bcol_t + 0][brow_t] = bv.x; Bs[bcol_t + 1][brow_t] = bv.y;
            Bs[bcol_t + 2][brow_t] = bv.z; Bs[bcol_t + 3][brow_t] = bv.w;
        } else {
            *(float4*)&Bs[brow_n][bcol_n] = bv;
        }
        __syncthreads();
#pragma unroll
        for (int kk = 0; kk < 8; kk++) {
            float a[8], b[8];
            *(float4*)(a    ) = *(const float4*)&As[kk][ty * 8];
            *(float4*)(a + 4) = *(const float4*)&As[kk][ty * 8 + 4];
            *(float4*)(b    ) = *(const float4*)&Bs[kk][tx * 8];
            *(float4*)(b + 4) = *(const float4*)&Bs[kk][tx * 8 + 4];
#pragma unroll
            for (int i = 0; i < 8; i++)
#pragma unroll
                for (int j = 0; j < 8; j++)
                    acc[i][j] = fmaf(a[i], b[j], acc[i][j]);
        }
    }

#pragma unroll
    for (int i = 0; i < 8; i++) {
        int m = m0 + ty * 8 + i;
        if (m >= M) continue;
        float rs = ROWSCALE ? rowscale[(size_t)m * rss] : 0.f;
#pragma unroll
        for (int j = 0; j < 8; j++) {
            int n = n0 + tx * 8 + j;
            if (n >= N) continue;
            float v = alpha * acc[i][j];
            if (bias) v += bias[n];
            if (DOGELU) v = 0.5f * v * (1.f + erff(v * 0.70710678118654752440f));
            if (addend) v += addend[(size_t)m * ldadd + n];
            size_t idx = (size_t)m * ldc + n;
            if (ROWSCALE)      C[idx] += rs * v;
            else if (ACCUM)    C[idx] += v;
            else               C[idx]  = v;
            if (C2) C2[idx] = v;
        }
    }
}

// ---------------- reductions -------------------------------------------------
__device__ __forceinline__ float warpMax(float v) {
#pragma unroll
    for (int o = 16; o; o >>= 1) v = fmaxf(v, __shfl_xor_sync(0xffffffffu, v, o));
    return v;
}
__device__ __forceinline__ float warpSum(float v) {
#pragma unroll
    for (int o = 16; o; o >>= 1) v += __shfl_xor_sync(0xffffffffu, v, o);
    return v;
}
// blockDim == 256 assumed
__device__ __forceinline__ float blockMax(float v) {
    __shared__ float sh[8]; __shared__ float res;
    v = warpMax(v);
    if ((threadIdx.x & 31) == 0) sh[threadIdx.x >> 5] = v;
    __syncthreads();
    if (threadIdx.x == 0) {
        float m = sh[0];
#pragma unroll
        for (int i = 1; i < 8; i++) m = fmaxf(m, sh[i]);
        res = m;
    }
    __syncthreads();
    float r = res;
    __syncthreads();
    return r;
}
__device__ __forceinline__ float blockSum(float v) {
    __shared__ float sh[8]; __shared__ float res;
    v = warpSum(v);
    if ((threadIdx.x & 31) == 0) sh[threadIdx.x >> 5] = v;
    __syncthreads();
    if (threadIdx.x == 0) {
        float m = 0.f;
#pragma unroll
        for (int i = 0; i < 8; i++) m += sh[i];
        res = m;
    }
    __syncthreads();
    float r = res;
    __syncthreads();
    return r;
}

// ---------------- softmax over rows of 2048 (in place) -----------------------
__global__ void __launch_bounds__(256) softmax2048_k(float* __restrict__ s) {
    const int tid = threadIdx.x;
    float* row = s + (size_t)blockIdx.x * SS;
    float v[8];
    float mx = -1e30f;
#pragma unroll
    for (int i = 0; i < 8; i++) { v[i] = row[tid + 256 * i]; mx = fmaxf(mx, v[i]); }
    mx = blockMax(mx);
    float sum = 0.f;
#pragma unroll
    for (int i = 0; i < 8; i++) { v[i] = expf(v[i] - mx); sum += v[i]; }
    sum = blockSum(sum);
    float inv = 1.f / sum;
#pragma unroll
    for (int i = 0; i < 8; i++) row[tid + 256 * i] = v[i] * inv;
}

// ---------------- top-k(204) threshold + masked softmax (in place) -----------
__global__ void __launch_bounds__(256) topk_softmax2048_k(float* __restrict__ s) {
    __shared__ unsigned uk[SS];
    __shared__ int icnt;
    const int tid = threadIdx.x;
    float* row = s + (size_t)blockIdx.x * SS;
    float v[8];
    unsigned myk[8];
    float mx = -1e30f;
#pragma unroll
    for (int i = 0; i < 8; i++) {
        float f = row[tid + 256 * i];
        v[i] = f;
        unsigned u = __float_as_uint(f);
        u = (u & 0x80000000u) ? ~u : (u | 0x80000000u);  // monotone key
        myk[i] = u;
        uk[tid + 256 * i] = u;
        mx = fmaxf(mx, f);
    }
    __syncthreads();
    // binary search for the largest key t with count(key >= t) >= KSP
    // (== key of the KSP-th largest element, ties included like jnp.where(s>=thr))
    unsigned ans = 0u;
    for (int bit = 31; bit >= 0; bit--) {
        unsigned cand = ans | (1u << bit);
        int c = 0;
#pragma unroll
        for (int i = 0; i < 8; i++) c += (uk[tid + 256 * i] >= cand) ? 1 : 0;
        c = warpSum(c);
        __syncthreads();
        if (tid == 0) icnt = 0;
        __syncthreads();
        if ((tid & 31) == 0) atomicAdd(&icnt, c);
        __syncthreads();
        if (icnt >= KSP) ans = cand;
    }
    mx = blockMax(mx);
    float sum = 0.f;
    float e[8];
#pragma unroll
    for (int i = 0; i < 8; i++) {
        bool inc = (myk[i] >= ans);
        e[i] = inc ? expf(v[i] - mx) : 0.f;
        sum += e[i];
    }
    sum = blockSum(sum);
    float inv = 1.f / sum;
#pragma unroll
    for (int i = 0; i < 8; i++) row[tid + 256 * i] = e[i] * inv;
}

// ---------------- softmax over rows of 64 (memory weights, in place) ---------
__global__ void __launch_bounds__(256) softmax64_k(float* __restrict__ s) {
    int lane = threadIdx.x & 31, w = threadIdx.x >> 5;
    size_t r = (size_t)blockIdx.x * 8 + w;
    float* row = s + r * MMEM;
    float a = row[lane], b = row[lane + 32];
    float mx = warpMax(fmaxf(a, b));
    float ea = expf(a - mx), eb = expf(b - mx);
    float sum = warpSum(ea + eb);
    float inv = 1.f / sum;
    row[lane] = ea * inv;
    row[lane + 32] = eb * inv;
}

// ---------------- router: rw = softmax(x2 @ Wr + br) over E=4 ----------------
__global__ void __launch_bounds__(256) router_k(
    const float* __restrict__ x2, const float* __restrict__ Wr,
    const float* __restrict__ br, float* __restrict__ rw)
{
    int lane = threadIdx.x & 31, w = threadIdx.x >> 5;
    size_t r = (size_t)blockIdx.x * 8 + w;
    const float* xr = x2 + r * DD;
    float a0 = 0.f, a1 = 0.f, a2 = 0.f, a3 = 0.f;
    for (int j = lane; j < DD; j += 32) {
        float xv = xr[j];
        float4 wv = *(const float4*)(Wr + (size_t)j * 4);
        a0 = fmaf(xv, wv.x, a0); a1 = fmaf(xv, wv.y, a1);
        a2 = fmaf(xv, wv.z, a2); a3 = fmaf(xv, wv.w, a3);
    }
    a0 = warpSum(a0); a1 = warpSum(a1); a2 = warpSum(a2); a3 = warpSum(a3);
    if (lane == 0) {
        float l0 = a0 + br[0], l1 = a1 + br[1], l2 = a2 + br[2], l3 = a3 + br[3];
        float mx = fmaxf(fmaxf(l0, l1), fmaxf(l2, l3));
        float e0 = expf(l0 - mx), e1 = expf(l1 - mx), e2 = expf(l2 - mx), e3 = expf(l3 - mx);
        float inv = 1.f / (e0 + e1 + e2 + e3);
        rw[r * 4 + 0] = e0 * inv; rw[r * 4 + 1] = e1 * inv;
        rw[r * 4 + 2] = e2 * inv; rw[r * 4 + 3] = e3 * inv;
    }
}

// ---------------- host-side GEMM dispatch ------------------------------------
static void launch_gemm(bool transb, bool dogelu, bool accum, bool rowscale,
                        const float* A, int lda, const float* Bm, int ldb,
                        float* C, int ldc, float* C2,
                        int M, int N, int K, float alpha,
                        const float* bias, const float* rs, int rss,
                        const float* addend, int ldadd)
{
    dim3 grid((N + 127) / 128, (M + 127) / 128), blk(256);
    if (transb)
        gemm_k<true, false, false, false><<<grid, blk>>>(A, lda, Bm, ldb, C, ldc, C2, M, N, K, alpha, bias, rs, rss, addend, ldadd);
    else if (dogelu)
        gemm_k<false, true, false, false><<<grid, blk>>>(A, lda, Bm, ldb, C, ldc, C2, M, N, K, alpha, bias, rs, rss, addend, ldadd);
    else if (accum)
        gemm_k<false, false, true, false><<<grid, blk>>>(A, lda, Bm, ldb, C, ldc, C2, M, N, K, alpha, bias, rs, rss, addend, ldadd);
    else if (rowscale)
        gemm_k<false, false, false, true><<<grid, blk>>>(A, lda, Bm, ldb, C, ldc, C2, M, N, K, alpha, bias, rs, rss, addend, ldadd);
    else
        gemm_k<false, false, false, false><<<grid, blk>>>(A, lda, Bm, ldb, C, ldc, C2, M, N, K, alpha, bias, rs, rss, addend, ldadd);
}

extern "C" void kernel_launch(void* const* d_in, const int* in_sizes, int n_in,
                              void* d_out, int out_size)
{
    const float* x      = (const float*)d_in[0];
    const float* WqkvL  = (const float*)d_in[1];
    const float* WqkvS  = (const float*)d_in[2];
    const float* membk  = (const float*)d_in[3];
    const float* Wm     = (const float*)d_in[4];
    const float* Wo     = (const float*)d_in[5];
    const float* bo     = (const float*)d_in[6];
    const float* Wi     = (const float*)d_in[7];
    const float* bi     = (const float*)d_in[8];
    const float* Wp1    = (const float*)d_in[9];
    const float* bp1    = (const float*)d_in[10];
    const float* Wp2    = (const float*)d_in[11];
    const float* bp2    = (const float*)d_in[12];
    const float* Wwb    = (const float*)d_in[13];
    const float* bwb    = (const float*)d_in[14];
    const float* Wr     = (const float*)d_in[15];
    const float* br     = (const float*)d_in[16];
    const float* We1    = (const float*)d_in[17];
    const float* be1    = (const float*)d_in[18];
    const float* We2    = (const float*)d_in[19];
    const float* be2    = (const float*)d_in[20];
    float* out = (float*)d_out;

    float *qkvL, *qkvS, *sc, *cat, *xp, *ret, *mlog, *pp, *mid, *x2, *rw, *h;
    cudaGetSymbolAddress((void**)&qkvL, g_qkv_loc);
    cudaGetSymbolAddress((void**)&qkvS, g_qkv_sp);
    cudaGetSymbolAddress((void**)&sc,   g_scores);
    cudaGetSymbolAddress((void**)&cat,  g_cat);
    cudaGetSymbolAddress((void**)&xp,   g_xp);
    cudaGetSymbolAddress((void**)&ret,  g_ret);
    cudaGetSymbolAddress((void**)&mlog, g_mlog);
    cudaGetSymbolAddress((void**)&pp,   g_pp);
    cudaGetSymbolAddress((void**)&mid,  g_mid);
    cudaGetSymbolAddress((void**)&x2,   g_x2);
    cudaGetSymbolAddress((void**)&rw,   g_rw);
    cudaGetSymbolAddress((void**)&h,    g_h);

    const float scale = 0.0625f;  // H^-0.5

    // --- QKV projections (local + sparse) ---
    launch_gemm(false, false, false, false, x, DD, WqkvL, 3 * HH, qkvL, 3 * HH, nullptr,
                BS, 3 * HH, DD, 1.f, nullptr, nullptr, 0, nullptr, 0);
    launch_gemm(false, false, false, false, x, DD, WqkvS, 3 * HH, qkvS, 3 * HH, nullptr,
                BS, 3 * HH, DD, 1.f, nullptr, nullptr, 0, nullptr, 0);

    // --- local attention ---
    for (int b = 0; b < BB; b++) {
        const float* qb = qkvL + (size_t)b * SS * 3 * HH;
        launch_gemm(true, false, false, false, qb, 3 * HH, qb + HH, 3 * HH,
                    sc + (size_t)b * SS * SS, SS, nullptr,
                    SS, SS, HH, scale, nullptr, nullptr, 0, nullptr, 0);
    }
    softmax2048_k<<<BS, 256>>>(sc);
    for (int b = 0; b < BB; b++) {
        launch_gemm(false, false, false, false, sc + (size_t)b * SS * SS, SS,
                    qkvL + (size_t)b * SS * 3 * HH + 2 * HH, 3 * HH,
                    cat + (size_t)b * SS * 4 * HH, 4 * HH, nullptr,
                    SS, HH, SS, 1.f, nullptr, nullptr, 0, nullptr, 0);
    }

    // --- sparse attention ---
    for (int b = 0; b < BB; b++) {
        const float* qb = qkvS + (size_t)b * SS * 3 * HH;
        launch_gemm(true, false, false, false, qb, 3 * HH, qb + HH, 3 * HH,
                    sc + (size_t)b * SS * SS, SS, nullptr,
                    SS, SS, HH, scale, nullptr, nullptr, 0, nullptr, 0);
    }
    topk_softmax2048_k<<<BS, 256>>>(sc);
    for (int b = 0; b < BB; b++) {
        launch_gemm(false, false, false, false, sc + (size_t)b * SS * SS, SS,
                    qkvS + (size_t)b * SS * 3 * HH + 2 * HH, 3 * HH,
                    cat + (size_t)b * SS * 4 * HH + HH, 4 * HH, nullptr,
                    SS, HH, SS, 1.f, nullptr, nullptr, 0, nullptr, 0);
    }

    // --- memory path ---
    launch_gemm(false, false, false, false, x, DD, Wm, HH, xp, HH, nullptr,
                BS, HH, DD, 1.f, nullptr, nullptr, 0, nullptr, 0);
    launch_gemm(true, false, false, false, xp, HH, membk, HH, mlog, MMEM, nullptr,
                BS, MMEM, HH, 1.f, nullptr, nullptr, 0, nullptr, 0);
    softmax64_k<<<BS / 8, 256>>>(mlog);
    launch_gemm(false, false, false, false, mlog, MMEM, membk, HH, ret, HH, nullptr,
                BS, HH, MMEM, 1.f, nullptr, nullptr, 0, nullptr, 0);
    // out_mem = xp @ Wo[0:256] + ret @ Wo[256:512] + bo  -> cat cols [512,768)
    launch_gemm(false, false, false, false, xp, HH, Wo, HH,
                cat + 2 * HH, 4 * HH, nullptr, BS, HH, HH, 1.f, nullptr, nullptr, 0, nullptr, 0);
    launch_gemm(false, false, true, false, ret, HH, Wo + (size_t)HH * HH, HH,
                cat + 2 * HH, 4 * HH, nullptr, BS, HH, HH, 1.f, bo, nullptr, 0, nullptr, 0);

    // --- predictive path ---
    launch_gemm(false, false, false, false, x, DD, Wi, HH, pp, HH, nullptr,
                BS, HH, DD, 1.f, bi, nullptr, 0, nullptr, 0);
    launch_gemm(false, true, false, false, pp, HH, Wp1, 2 * HH, mid, 2 * HH, nullptr,
                BS, 2 * HH, HH, 1.f, bp1, nullptr, 0, nullptr, 0);
    launch_gemm(false, false, false, false, mid, 2 * HH, Wp2, HH,
                cat + 3 * HH, 4 * HH, nullptr, BS, HH, 2 * HH, 1.f, bp2, nullptr, 0, nullptr, 0);

    // --- hydra combine + residual: x2 = x + cat @ Wwb + bwb (also into d_out) ---
    launch_gemm(false, false, false, false, cat, 4 * HH, Wwb, DD, x2, DD, out,
                BS, DD, 4 * HH, 1.f, bwb, nullptr, 0, x, DD);

    // --- router ---
    router_k<<<BS / 8, 256>>>(x2, Wr, br, rw);

    // --- MoE: out += rw[:,e] * (gelu(x2@We1[e]+be1[e]) @ We2[e] + be2[e]) ---
    for (int e = 0; e < EE; e++) {
        launch_gemm(false, true, false, false, x2, DD,
                    We1 + (size_t)e * DD * FF, FF, h, FF, nullptr,
                    BS, FF, DD, 1.f, be1 + (size_t)e * FF, nullptr, 0, nullptr, 0);
        launch_gemm(false, false, false, true, h, FF,
                    We2 + (size_t)e * FF * DD, DD, out, DD, nullptr,
                    BS, DD, FF, 1.f, be2 + (size_t)e * DD, rw + e, EE, nullptr, 0);
    }
}